// round 13
// baseline (speedup 1.0000x reference)
#include <cuda_runtime.h>
#include <stdint.h>

// kNN: B=2, N=2048, D=16, K=16. Output (B,N,K,2) FLOAT32: [b, idx].
//
// R12 (43.3us) -> ONE WARP PER QUERY: merge cost amortized over 64 steps
// instead of 32, no cross-warp coupling, grid fits one wave (1024 CTAs,
// 9 CTAs/SM at 128 threads).
//  - Distance via packed f32x2 FMA (fma.rn.f32x2 -> FFMA2), candidates as
//    ulonglong2 from SoA scratch (coalesced).
//  - Per-lane sorted top-6 branchy insert (stable strict-<, ties -> lower
//    index = jax.lax.top_k semantics).
//  - 16-round warp-min pop merge over 64-bit keys (dist_bits<<32|idx);
//    lane r captures round-r winner, lanes 0..15 write output directly.
//  - Guard: lane popping all 6 -> exact depth-16 SMEM fallback
//    (P ~= 32*P(Bin(16,1/32)>=6) ~= 1.7e-4/warp => ~0.7 warps/launch).

#define NPTS 2048
#define KNN  16
#define KL   6
#define WPC  4                     // 4 warps = 4 queries per CTA
#define THREADS (WPC * 32)
#define NSTEPS 64                  // 2048 candidates / 32 lanes

__device__ float4 T4g[2][4][NPTS];   // 256 KB static scratch

__global__ void transpose_kernel(const float* __restrict__ points)
{
    int idx = blockIdx.x * blockDim.x + threadIdx.x;   // b*8192 + c*2048 + j
    if (idx >= 2 * 4 * NPTS) return;
    int j = idx & (NPTS - 1);
    int c = (idx >> 11) & 3;
    int b = idx >> 13;
    const float4* P4 = reinterpret_cast<const float4*>(points);
    T4g[b][c][j] = P4[(b * NPTS + j) * 4 + c];
}

__device__ __forceinline__ unsigned long long ffma2(
    unsigned long long a, unsigned long long bb, unsigned long long c)
{
    unsigned long long r;
    asm("fma.rn.f32x2 %0, %1, %2, %3;" : "=l"(r) : "l"(a), "l"(bb), "l"(c));
    return r;
}

#define NEG1X2 0xBF800000BF800000ull   // packed (-1.0f, -1.0f)

// Packed distance key: d = fma(a, -1, q) (== q-a, single rounding), s += d*d;
// combine even/odd partials, sqrt, return float bits (compare post-sqrt).
__device__ __forceinline__ unsigned dist_key_p(const unsigned long long* qp,
                                               int b, int j)
{
    const ulonglong2* P0 = reinterpret_cast<const ulonglong2*>(T4g[b][0]);
    const ulonglong2* P1 = reinterpret_cast<const ulonglong2*>(T4g[b][1]);
    const ulonglong2* P2 = reinterpret_cast<const ulonglong2*>(T4g[b][2]);
    const ulonglong2* P3 = reinterpret_cast<const ulonglong2*>(T4g[b][3]);
    ulonglong2 a0 = P0[j], a1 = P1[j], a2 = P2[j], a3 = P3[j];

    unsigned long long s = 0ull, d;
    d = ffma2(a0.x, NEG1X2, qp[0]); s = ffma2(d, d, s);
    d = ffma2(a0.y, NEG1X2, qp[1]); s = ffma2(d, d, s);
    d = ffma2(a1.x, NEG1X2, qp[2]); s = ffma2(d, d, s);
    d = ffma2(a1.y, NEG1X2, qp[3]); s = ffma2(d, d, s);
    d = ffma2(a2.x, NEG1X2, qp[4]); s = ffma2(d, d, s);
    d = ffma2(a2.y, NEG1X2, qp[5]); s = ffma2(d, d, s);
    d = ffma2(a3.x, NEG1X2, qp[6]); s = ffma2(d, d, s);
    d = ffma2(a3.y, NEG1X2, qp[7]); s = ffma2(d, d, s);

    unsigned lo, hi;
    asm("mov.b64 {%0, %1}, %2;" : "=r"(lo), "=r"(hi) : "l"(s));
    float sum = __uint_as_float(lo) + __uint_as_float(hi);
    return __float_as_uint(__fsqrt_rn(sum));
}

__device__ __forceinline__ unsigned long long umin64(unsigned long long a,
                                                     unsigned long long b)
{ return (b < a) ? b : a; }

__global__ __launch_bounds__(THREADS, 9)
void knn_kernel(float2* __restrict__ out)
{
    __shared__ unsigned sD[WPC][KNN][32];            // fallback scratch (rare)
    __shared__ int      sJ[WPC][KNN][32];

    const int b    = blockIdx.y;
    const int wid  = threadIdx.x >> 5;
    const int lane = threadIdx.x & 31;
    const int q    = blockIdx.x * WPC + wid;         // 0..2047

    // Query point, packed pairs (dims 2i, 2i+1).
    unsigned long long qp[8];
    {
        const ulonglong2* P0 = reinterpret_cast<const ulonglong2*>(T4g[b][0]);
        const ulonglong2* P1 = reinterpret_cast<const ulonglong2*>(T4g[b][1]);
        const ulonglong2* P2 = reinterpret_cast<const ulonglong2*>(T4g[b][2]);
        const ulonglong2* P3 = reinterpret_cast<const ulonglong2*>(T4g[b][3]);
        ulonglong2 t;
        t = P0[q]; qp[0] = t.x; qp[1] = t.y;
        t = P1[q]; qp[2] = t.x; qp[3] = t.y;
        t = P2[q]; qp[4] = t.x; qp[5] = t.y;
        t = P3[q]; qp[6] = t.x; qp[7] = t.y;
    }

    // ---- Pass over 2048 candidates: per-lane sorted top-6 ----
    unsigned D[KL];
    int      J[KL];
#pragma unroll
    for (int i = 0; i < KL; ++i) { D[i] = 0xFFFFFFFFu; J[i] = 0x7FFFFFFF; }

#pragma unroll 2
    for (int t = 0; t < NSTEPS; ++t) {
        const int j = t * 32 + lane;
        unsigned kb = dist_key_p(qp, b, j);
        if (j == q) kb = 0xFFFFFFFFu;                // exclude self

        if (kb < D[KL - 1]) {                        // stable strict-<
            D[KL - 1] = kb; J[KL - 1] = j;
#pragma unroll
            for (int i = KL - 1; i > 0; --i) {
                if (D[i] < D[i - 1]) {
                    unsigned td = D[i]; D[i] = D[i - 1]; D[i - 1] = td;
                    int      tj = J[i]; J[i] = J[i - 1]; J[i - 1] = tj;
                }
            }
        }
    }

    // ---- 16-round warp-min pop merge; lane r captures round-r winner ----
    unsigned long long keep = 0xFFFFFFFFFFFFFFFFull;
    int cnt = 0;
    unsigned long long h = ((unsigned long long)D[0] << 32) | (unsigned)J[0];
#pragma unroll
    for (int r = 0; r < KNN; ++r) {
        unsigned long long v = h;
#pragma unroll
        for (int off = 16; off > 0; off >>= 1)
            v = umin64(v, __shfl_xor_sync(0xFFFFFFFFu, v, off));
        if (lane == r) keep = v;
        if (h == v) {                                // real keys unique
            ++cnt;
#pragma unroll
            for (int i = 0; i < KL - 1; ++i) { D[i] = D[i + 1]; J[i] = J[i + 1]; }
            D[KL - 1] = 0xFFFFFFFFu; J[KL - 1] = 0x7FFFFFFF;
            h = ((unsigned long long)D[0] << 32) | (unsigned)J[0];
        }
    }

    // ---- Guard: fully-popped lane may have discarded a needed 7th entry ----
    if (__ballot_sync(0xFFFFFFFFu, cnt == KL) != 0) {
#pragma unroll 1
        for (int i = 0; i < KNN; ++i) { sD[wid][i][lane] = 0xFFFFFFFFu; sJ[wid][i][lane] = 0x7FFFFFFF; }
#pragma unroll 1
        for (int t = 0; t < NSTEPS; ++t) {
            const int j = t * 32 + lane;
            unsigned kk = dist_key_p(qp, b, j);      // same bits as fast path
            if (j == q) continue;
            if (kk < sD[wid][KNN - 1][lane]) {
                int p = KNN - 1;
#pragma unroll 1
                while (p > 0 && kk < sD[wid][p - 1][lane]) {
                    sD[wid][p][lane] = sD[wid][p - 1][lane];
                    sJ[wid][p][lane] = sJ[wid][p - 1][lane];
                    --p;
                }
                sD[wid][p][lane] = kk; sJ[wid][p][lane] = j;
            }
        }
        int cur = 0;
        unsigned long long h2 = ((unsigned long long)sD[wid][0][lane] << 32)
                              | (unsigned)sJ[wid][0][lane];
#pragma unroll 1
        for (int r = 0; r < KNN; ++r) {
            unsigned long long v = h2;
#pragma unroll
            for (int off = 16; off > 0; off >>= 1)
                v = umin64(v, __shfl_xor_sync(0xFFFFFFFFu, v, off));
            if (lane == r) keep = v;
            if (h2 == v) {
                ++cur;
                h2 = (cur < KNN)
                   ? (((unsigned long long)sD[wid][cur][lane] << 32) | (unsigned)sJ[wid][cur][lane])
                   : 0xFFFFFFFFFFFFFFFFull;
            }
        }
    }

    // ---- Output: lane r holds the r-th nearest neighbor ----
    if (lane < KNN) {
        float2* outp = out + ((size_t)b * NPTS + q) * KNN;
        outp[lane] = make_float2((float)b,
                                 (float)(int)(unsigned)(keep & 0xFFFFFFFFull));
    }
}

extern "C" void kernel_launch(void* const* d_in, const int* in_sizes, int n_in,
                              void* d_out, int out_size)
{
    // points (2*2048*16) is the SMALLER input (features is 4x larger).
    const float* points;
    if (n_in >= 2) {
        points = (in_sizes[0] <= in_sizes[1]) ? (const float*)d_in[0]
                                              : (const float*)d_in[1];
    } else {
        points = (const float*)d_in[0];
    }

    transpose_kernel<<<(2 * 4 * NPTS + 255) / 256, 256>>>(points);

    dim3 grid(NPTS / WPC, 2);        // 4 queries per CTA (4 warps), 1024 CTAs
    knn_kernel<<<grid, THREADS>>>((float2*)d_out);
}

// round 14
// speedup vs baseline: 2.6918x; 2.6918x over previous
#include <cuda_runtime.h>
#include <stdint.h>

// kNN: B=2, N=2048, D=16, K=16. Output (B,N,K,2) FLOAT32: [b, idx].
//
// R12 architecture (best 43.3us: 2 warps/query, 128-thr CTAs, KL=6) plus:
//  1) Pop-merge rounds use __reduce_min_sync (REDUX) twice instead of a
//     5-stage 64-bit shfl reduce: m = min(head_key); jw = min(j | key==m).
//     Exact same winner incl. tie -> lower index.
//  2) dist_key_p uses two independent packed ffma2 chains (halves the
//     serial FP latency per candidate).
// Unchanged: SoA transpose, per-lane sorted top-6 branchy insert (stable
// strict-<), cross-half bitonic pair merge, exact depth-16 SMEM fallback
// guard (P ~ 1.7e-4/warp).

#define NPTS 2048
#define KNN  16
#define KL   6
#define WPC  4                     // 4 warps = 2 queries per CTA
#define THREADS (WPC * 32)
#define HALF_STEPS 32              // 1024 candidates / 32 lanes

__device__ float4 T4g[2][4][NPTS];   // 256 KB static scratch

__global__ void transpose_kernel(const float* __restrict__ points)
{
    int idx = blockIdx.x * blockDim.x + threadIdx.x;   // b*8192 + c*2048 + j
    if (idx >= 2 * 4 * NPTS) return;
    int j = idx & (NPTS - 1);
    int c = (idx >> 11) & 3;
    int b = idx >> 13;
    const float4* P4 = reinterpret_cast<const float4*>(points);
    T4g[b][c][j] = P4[(b * NPTS + j) * 4 + c];
}

__device__ __forceinline__ unsigned long long ffma2(
    unsigned long long a, unsigned long long bb, unsigned long long c)
{
    unsigned long long r;
    asm("fma.rn.f32x2 %0, %1, %2, %3;" : "=l"(r) : "l"(a), "l"(bb), "l"(c));
    return r;
}
__device__ __forceinline__ unsigned long long addf2(
    unsigned long long a, unsigned long long bb)
{
    unsigned long long r;
    asm("add.rn.f32x2 %0, %1, %2;" : "=l"(r) : "l"(a), "l"(bb));
    return r;
}

#define NEG1X2 0xBF800000BF800000ull   // packed (-1.0f, -1.0f)

// Packed distance key, two independent accumulator chains.
__device__ __forceinline__ unsigned dist_key_p(const unsigned long long* qp,
                                               int b, int j)
{
    const ulonglong2* P0 = reinterpret_cast<const ulonglong2*>(T4g[b][0]);
    const ulonglong2* P1 = reinterpret_cast<const ulonglong2*>(T4g[b][1]);
    const ulonglong2* P2 = reinterpret_cast<const ulonglong2*>(T4g[b][2]);
    const ulonglong2* P3 = reinterpret_cast<const ulonglong2*>(T4g[b][3]);
    ulonglong2 a0 = P0[j], a1 = P1[j], a2 = P2[j], a3 = P3[j];

    unsigned long long sa = 0ull, sb = 0ull, d;
    d = ffma2(a0.x, NEG1X2, qp[0]); sa = ffma2(d, d, sa);
    d = ffma2(a0.y, NEG1X2, qp[1]); sb = ffma2(d, d, sb);
    d = ffma2(a1.x, NEG1X2, qp[2]); sa = ffma2(d, d, sa);
    d = ffma2(a1.y, NEG1X2, qp[3]); sb = ffma2(d, d, sb);
    d = ffma2(a2.x, NEG1X2, qp[4]); sa = ffma2(d, d, sa);
    d = ffma2(a2.y, NEG1X2, qp[5]); sb = ffma2(d, d, sb);
    d = ffma2(a3.x, NEG1X2, qp[6]); sa = ffma2(d, d, sa);
    d = ffma2(a3.y, NEG1X2, qp[7]); sb = ffma2(d, d, sb);
    unsigned long long s = addf2(sa, sb);

    unsigned lo, hi;
    asm("mov.b64 {%0, %1}, %2;" : "=r"(lo), "=r"(hi) : "l"(s));
    float sum = __uint_as_float(lo) + __uint_as_float(hi);
    return __float_as_uint(__fsqrt_rn(sum));        // compare post-sqrt
}

__device__ __forceinline__ unsigned long long umin64(unsigned long long a,
                                                     unsigned long long b)
{ return (b < a) ? b : a; }
__device__ __forceinline__ unsigned long long umax64(unsigned long long a,
                                                     unsigned long long b)
{ return (a < b) ? b : a; }

__global__ __launch_bounds__(THREADS, 9)
void knn_kernel(float2* __restrict__ out)
{
    __shared__ unsigned sD[WPC][KNN][32];            // fallback scratch (rare)
    __shared__ int      sJ[WPC][KNN][32];
    __shared__ unsigned long long sX[WPC][16];       // pair exchange

    const int b    = blockIdx.y;
    const int wid  = threadIdx.x >> 5;
    const int lane = threadIdx.x & 31;
    const int pair = wid >> 1;
    const int half = wid & 1;
    const int q    = blockIdx.x * 2 + pair;          // 0..2047
    const int jbase = half * (NPTS / 2);             // this warp's candidate half

    // Query point, packed pairs (dims 2i, 2i+1).
    unsigned long long qp[8];
    {
        const ulonglong2* P0 = reinterpret_cast<const ulonglong2*>(T4g[b][0]);
        const ulonglong2* P1 = reinterpret_cast<const ulonglong2*>(T4g[b][1]);
        const ulonglong2* P2 = reinterpret_cast<const ulonglong2*>(T4g[b][2]);
        const ulonglong2* P3 = reinterpret_cast<const ulonglong2*>(T4g[b][3]);
        ulonglong2 t;
        t = P0[q]; qp[0] = t.x; qp[1] = t.y;
        t = P1[q]; qp[2] = t.x; qp[3] = t.y;
        t = P2[q]; qp[4] = t.x; qp[5] = t.y;
        t = P3[q]; qp[6] = t.x; qp[7] = t.y;
    }

    // ---- Pass over 1024 candidates: per-lane sorted top-6 ----
    unsigned D[KL];
    int      J[KL];
#pragma unroll
    for (int i = 0; i < KL; ++i) { D[i] = 0xFFFFFFFFu; J[i] = 0x7FFFFFFF; }

#pragma unroll 2
    for (int t = 0; t < HALF_STEPS; ++t) {
        const int j = jbase + t * 32 + lane;
        unsigned kb = dist_key_p(qp, b, j);
        if (j == q) kb = 0xFFFFFFFFu;                // exclude self

        if (kb < D[KL - 1]) {                        // stable strict-<
            D[KL - 1] = kb; J[KL - 1] = j;
#pragma unroll
            for (int i = KL - 1; i > 0; --i) {
                if (D[i] < D[i - 1]) {
                    unsigned td = D[i]; D[i] = D[i - 1]; D[i - 1] = td;
                    int      tj = J[i]; J[i] = J[i - 1]; J[i - 1] = tj;
                }
            }
        }
    }

    // ---- 16-round REDUX pop merge; lane r captures round-r winner ----
    unsigned long long keep = 0xFFFFFFFFFFFFFFFFull;
    int cnt = 0;
#pragma unroll
    for (int r = 0; r < KNN; ++r) {
        unsigned hk = D[0];
        unsigned m  = __reduce_min_sync(0xFFFFFFFFu, hk);
        unsigned ji = (hk == m) ? (unsigned)J[0] : 0x7FFFFFFFu;
        unsigned jw = __reduce_min_sync(0xFFFFFFFFu, ji);   // tie -> lower idx
        if (lane == r)
            keep = ((unsigned long long)m << 32) | jw;
        if (hk == m && (unsigned)J[0] == jw) {       // exactly one lane pops
            ++cnt;
#pragma unroll
            for (int i = 0; i < KL - 1; ++i) { D[i] = D[i + 1]; J[i] = J[i + 1]; }
            D[KL - 1] = 0xFFFFFFFFu; J[KL - 1] = 0x7FFFFFFF;
        }
    }

    // ---- Guard: fully-popped lane may have discarded a needed 7th entry ----
    if (__ballot_sync(0xFFFFFFFFu, cnt == KL) != 0) {
#pragma unroll 1
        for (int i = 0; i < KNN; ++i) { sD[wid][i][lane] = 0xFFFFFFFFu; sJ[wid][i][lane] = 0x7FFFFFFF; }
#pragma unroll 1
        for (int t = 0; t < HALF_STEPS; ++t) {
            const int j = jbase + t * 32 + lane;
            unsigned kk = dist_key_p(qp, b, j);      // same bits as fast path
            if (j == q) continue;
            if (kk < sD[wid][KNN - 1][lane]) {
                int p = KNN - 1;
#pragma unroll 1
                while (p > 0 && kk < sD[wid][p - 1][lane]) {
                    sD[wid][p][lane] = sD[wid][p - 1][lane];
                    sJ[wid][p][lane] = sJ[wid][p - 1][lane];
                    --p;
                }
                sD[wid][p][lane] = kk; sJ[wid][p][lane] = j;
            }
        }
        int cur = 0;
#pragma unroll 1
        for (int r = 0; r < KNN; ++r) {
            unsigned hk = (cur < KNN) ? sD[wid][cur][lane] : 0xFFFFFFFFu;
            unsigned hj = (cur < KNN) ? (unsigned)sJ[wid][cur][lane] : 0x7FFFFFFFu;
            unsigned m  = __reduce_min_sync(0xFFFFFFFFu, hk);
            unsigned ji = (hk == m) ? hj : 0x7FFFFFFFu;
            unsigned jw = __reduce_min_sync(0xFFFFFFFFu, ji);
            if (lane == r)
                keep = ((unsigned long long)m << 32) | jw;
            if (hk == m && hj == jw) ++cur;
        }
    }

    // ---- Exchange + cross-half bitonic merge (even warp of each pair) ----
    if (lane < 16) sX[wid][lane] = keep;
    __syncthreads();

    if (half == 0) {
        // lanes 0..15: own ascending list; lanes 16..31: partner reversed.
        unsigned long long X = (lane < 16) ? keep : sX[wid + 1][31 - lane];
#pragma unroll
        for (int off = 16; off > 0; off >>= 1) {
            unsigned long long o = __shfl_xor_sync(0xFFFFFFFFu, X, off);
            X = (lane & off) ? umax64(X, o) : umin64(X, o);
        }
        if (lane < 16) {
            float2* outp = out + ((size_t)b * NPTS + q) * KNN;
            outp[lane] = make_float2((float)b,
                                     (float)(int)(unsigned)(X & 0xFFFFFFFFull));
        }
    }
}

extern "C" void kernel_launch(void* const* d_in, const int* in_sizes, int n_in,
                              void* d_out, int out_size)
{
    // points (2*2048*16) is the SMALLER input (features is 4x larger).
    const float* points;
    if (n_in >= 2) {
        points = (in_sizes[0] <= in_sizes[1]) ? (const float*)d_in[0]
                                              : (const float*)d_in[1];
    } else {
        points = (const float*)d_in[0];
    }

    transpose_kernel<<<(2 * 4 * NPTS + 255) / 256, 256>>>(points);

    dim3 grid(NPTS / 2, 2);          // 2 queries per CTA (4 warps), 2048 CTAs
    knn_kernel<<<grid, THREADS>>>((float2*)d_out);
}

// round 15
// speedup vs baseline: 2.6941x; 1.0009x over previous
#include <cuda_runtime.h>
#include <stdint.h>

// kNN: B=2, N=2048, D=16, K=16. Output (B,N,K,2) FLOAT32: [b, idx].
//
// R14 (37.4us) + cursor-based merge: per-lane sorted-6 lists stored to SMEM
// once after the pass; each pop refills the head via 2 conflict-free LDS at a
// per-lane cursor instead of a 12-instr register shift. Cursor clamped at
// KL-1; a lane popping all 6 trips the existing exact depth-16 fallback
// (P ~ 1.7e-4/warp), which recomputes everything, so the clamp is safe.
// Unchanged: 2 warps/query, 128-thr CTAs, packed dual-ffma2 distance,
// per-lane sorted top-6 branchy insert (stable strict-<, ties -> lower index
// = jax.lax.top_k), REDUX pop-merge winner rule, bitonic pair merge.

#define NPTS 2048
#define KNN  16
#define KL   6
#define WPC  4                     // 4 warps = 2 queries per CTA
#define THREADS (WPC * 32)
#define HALF_STEPS 32              // 1024 candidates / 32 lanes

__device__ float4 T4g[2][4][NPTS];   // 256 KB static scratch

__global__ void transpose_kernel(const float* __restrict__ points)
{
    int idx = blockIdx.x * blockDim.x + threadIdx.x;   // b*8192 + c*2048 + j
    if (idx >= 2 * 4 * NPTS) return;
    int j = idx & (NPTS - 1);
    int c = (idx >> 11) & 3;
    int b = idx >> 13;
    const float4* P4 = reinterpret_cast<const float4*>(points);
    T4g[b][c][j] = P4[(b * NPTS + j) * 4 + c];
}

__device__ __forceinline__ unsigned long long ffma2(
    unsigned long long a, unsigned long long bb, unsigned long long c)
{
    unsigned long long r;
    asm("fma.rn.f32x2 %0, %1, %2, %3;" : "=l"(r) : "l"(a), "l"(bb), "l"(c));
    return r;
}
__device__ __forceinline__ unsigned long long addf2(
    unsigned long long a, unsigned long long bb)
{
    unsigned long long r;
    asm("add.rn.f32x2 %0, %1, %2;" : "=l"(r) : "l"(a), "l"(bb));
    return r;
}

#define NEG1X2 0xBF800000BF800000ull   // packed (-1.0f, -1.0f)

// Packed distance key, two independent accumulator chains.
__device__ __forceinline__ unsigned dist_key_p(const unsigned long long* qp,
                                               int b, int j)
{
    const ulonglong2* P0 = reinterpret_cast<const ulonglong2*>(T4g[b][0]);
    const ulonglong2* P1 = reinterpret_cast<const ulonglong2*>(T4g[b][1]);
    const ulonglong2* P2 = reinterpret_cast<const ulonglong2*>(T4g[b][2]);
    const ulonglong2* P3 = reinterpret_cast<const ulonglong2*>(T4g[b][3]);
    ulonglong2 a0 = P0[j], a1 = P1[j], a2 = P2[j], a3 = P3[j];

    unsigned long long sa = 0ull, sb = 0ull, d;
    d = ffma2(a0.x, NEG1X2, qp[0]); sa = ffma2(d, d, sa);
    d = ffma2(a0.y, NEG1X2, qp[1]); sb = ffma2(d, d, sb);
    d = ffma2(a1.x, NEG1X2, qp[2]); sa = ffma2(d, d, sa);
    d = ffma2(a1.y, NEG1X2, qp[3]); sb = ffma2(d, d, sb);
    d = ffma2(a2.x, NEG1X2, qp[4]); sa = ffma2(d, d, sa);
    d = ffma2(a2.y, NEG1X2, qp[5]); sb = ffma2(d, d, sb);
    d = ffma2(a3.x, NEG1X2, qp[6]); sa = ffma2(d, d, sa);
    d = ffma2(a3.y, NEG1X2, qp[7]); sb = ffma2(d, d, sb);
    unsigned long long s = addf2(sa, sb);

    unsigned lo, hi;
    asm("mov.b64 {%0, %1}, %2;" : "=r"(lo), "=r"(hi) : "l"(s));
    float sum = __uint_as_float(lo) + __uint_as_float(hi);
    return __float_as_uint(__fsqrt_rn(sum));        // compare post-sqrt
}

__device__ __forceinline__ unsigned long long umin64(unsigned long long a,
                                                     unsigned long long b)
{ return (b < a) ? b : a; }
__device__ __forceinline__ unsigned long long umax64(unsigned long long a,
                                                     unsigned long long b)
{ return (a < b) ? b : a; }

__global__ __launch_bounds__(THREADS, 9)
void knn_kernel(float2* __restrict__ out)
{
    __shared__ unsigned sD[WPC][KNN][32];            // lists + fallback scratch
    __shared__ int      sJ[WPC][KNN][32];
    __shared__ unsigned long long sX[WPC][16];       // pair exchange

    const int b    = blockIdx.y;
    const int wid  = threadIdx.x >> 5;
    const int lane = threadIdx.x & 31;
    const int pair = wid >> 1;
    const int half = wid & 1;
    const int q    = blockIdx.x * 2 + pair;          // 0..2047
    const int jbase = half * (NPTS / 2);             // this warp's candidate half

    // Query point, packed pairs (dims 2i, 2i+1).
    unsigned long long qp[8];
    {
        const ulonglong2* P0 = reinterpret_cast<const ulonglong2*>(T4g[b][0]);
        const ulonglong2* P1 = reinterpret_cast<const ulonglong2*>(T4g[b][1]);
        const ulonglong2* P2 = reinterpret_cast<const ulonglong2*>(T4g[b][2]);
        const ulonglong2* P3 = reinterpret_cast<const ulonglong2*>(T4g[b][3]);
        ulonglong2 t;
        t = P0[q]; qp[0] = t.x; qp[1] = t.y;
        t = P1[q]; qp[2] = t.x; qp[3] = t.y;
        t = P2[q]; qp[4] = t.x; qp[5] = t.y;
        t = P3[q]; qp[6] = t.x; qp[7] = t.y;
    }

    // ---- Pass over 1024 candidates: per-lane sorted top-6 ----
    unsigned D[KL];
    int      J[KL];
#pragma unroll
    for (int i = 0; i < KL; ++i) { D[i] = 0xFFFFFFFFu; J[i] = 0x7FFFFFFF; }

#pragma unroll 2
    for (int t = 0; t < HALF_STEPS; ++t) {
        const int j = jbase + t * 32 + lane;
        unsigned kb = dist_key_p(qp, b, j);
        if (j == q) kb = 0xFFFFFFFFu;                // exclude self

        if (kb < D[KL - 1]) {                        // stable strict-<
            D[KL - 1] = kb; J[KL - 1] = j;
#pragma unroll
            for (int i = KL - 1; i > 0; --i) {
                if (D[i] < D[i - 1]) {
                    unsigned td = D[i]; D[i] = D[i - 1]; D[i - 1] = td;
                    int      tj = J[i]; J[i] = J[i - 1]; J[i - 1] = tj;
                }
            }
        }
    }

    // ---- Spill sorted lists to SMEM (conflict-free: bank == lane) ----
#pragma unroll
    for (int i = 0; i < KL; ++i) { sD[wid][i][lane] = D[i]; sJ[wid][i][lane] = J[i]; }

    // ---- 16-round REDUX pop merge with SMEM cursor refill ----
    unsigned long long keep = 0xFFFFFFFFFFFFFFFFull;
    int cur = 0;                                     // pops by this lane
    unsigned hk = D[0];
    unsigned hj = (unsigned)J[0];
#pragma unroll
    for (int r = 0; r < KNN; ++r) {
        unsigned m  = __reduce_min_sync(0xFFFFFFFFu, hk);
        unsigned ji = (hk == m) ? hj : 0x7FFFFFFFu;
        unsigned jw = __reduce_min_sync(0xFFFFFFFFu, ji);   // tie -> lower idx
        if (lane == r)
            keep = ((unsigned long long)m << 32) | jw;
        if (hk == m && hj == jw) {                   // this lane popped
            ++cur;
            int ic = (cur < KL) ? cur : (KL - 1);    // clamp; cur>=KL -> fallback
            hk = sD[wid][ic][lane];
            hj = (unsigned)sJ[wid][ic][lane];
        }
    }

    // ---- Guard: lane popping all 6 => rerun exact at depth 16 ----
    if (__ballot_sync(0xFFFFFFFFu, cur >= KL) != 0) {
#pragma unroll 1
        for (int i = 0; i < KNN; ++i) { sD[wid][i][lane] = 0xFFFFFFFFu; sJ[wid][i][lane] = 0x7FFFFFFF; }
#pragma unroll 1
        for (int t = 0; t < HALF_STEPS; ++t) {
            const int j = jbase + t * 32 + lane;
            unsigned kk = dist_key_p(qp, b, j);      // same bits as fast path
            if (j == q) continue;
            if (kk < sD[wid][KNN - 1][lane]) {
                int p = KNN - 1;
#pragma unroll 1
                while (p > 0 && kk < sD[wid][p - 1][lane]) {
                    sD[wid][p][lane] = sD[wid][p - 1][lane];
                    sJ[wid][p][lane] = sJ[wid][p - 1][lane];
                    --p;
                }
                sD[wid][p][lane] = kk; sJ[wid][p][lane] = j;
            }
        }
        int c2 = 0;
        unsigned fk = sD[wid][0][lane];
        unsigned fj = (unsigned)sJ[wid][0][lane];
#pragma unroll 1
        for (int r = 0; r < KNN; ++r) {
            unsigned m  = __reduce_min_sync(0xFFFFFFFFu, fk);
            unsigned ji = (fk == m) ? fj : 0x7FFFFFFFu;
            unsigned jw = __reduce_min_sync(0xFFFFFFFFu, ji);
            if (lane == r)
                keep = ((unsigned long long)m << 32) | jw;
            if (fk == m && fj == jw) {
                ++c2;
                if (c2 < KNN) {
                    fk = sD[wid][c2][lane];
                    fj = (unsigned)sJ[wid][c2][lane];
                } else {
                    fk = 0xFFFFFFFFu; fj = 0x7FFFFFFFu;
                }
            }
        }
    }

    // ---- Exchange + cross-half bitonic merge (even warp of each pair) ----
    if (lane < 16) sX[wid][lane] = keep;
    __syncthreads();

    if (half == 0) {
        // lanes 0..15: own ascending list; lanes 16..31: partner reversed.
        unsigned long long X = (lane < 16) ? keep : sX[wid + 1][31 - lane];
#pragma unroll
        for (int off = 16; off > 0; off >>= 1) {
            unsigned long long o = __shfl_xor_sync(0xFFFFFFFFu, X, off);
            X = (lane & off) ? umax64(X, o) : umin64(X, o);
        }
        if (lane < 16) {
            float2* outp = out + ((size_t)b * NPTS + q) * KNN;
            outp[lane] = make_float2((float)b,
                                     (float)(int)(unsigned)(X & 0xFFFFFFFFull));
        }
    }
}

extern "C" void kernel_launch(void* const* d_in, const int* in_sizes, int n_in,
                              void* d_out, int out_size)
{
    // points (2*2048*16) is the SMALLER input (features is 4x larger).
    const float* points;
    if (n_in >= 2) {
        points = (in_sizes[0] <= in_sizes[1]) ? (const float*)d_in[0]
                                              : (const float*)d_in[1];
    } else {
        points = (const float*)d_in[0];
    }

    transpose_kernel<<<(2 * 4 * NPTS + 255) / 256, 256>>>(points);

    dim3 grid(NPTS / 2, 2);          // 2 queries per CTA (4 warps), 2048 CTAs
    knn_kernel<<<grid, THREADS>>>((float2*)d_out);
}